// round 3
// baseline (speedup 1.0000x reference)
#include <cuda_runtime.h>
#include <cuda_bf16.h>
#include <cstddef>

// ---------------------------------------------------------------------------
// GAT_29437705846970: 4-layer GATConv (PyG semantics) + residual projection.
//   layer dims: 256->96, 96->96, 96->96, 96->48
//   N = 50000 nodes, E = 800000 edges (+ N self-loops appended)
// Output: x after 4 layers -> [N,48] f32
// ---------------------------------------------------------------------------

constexpr int N_NODES = 50000;
constexpr int N_EDGES = 800000;
constexpr int TOT_E   = N_EDGES + N_NODES;   // edges + self loops
constexpr float NEG_SLOPE = 0.2f;

// ---- scratch (device globals: no allocation allowed) ----------------------
__device__ float g_h  [(size_t)N_NODES * 96];   // h = x @ W
__device__ float g_res[(size_t)N_NODES * 96];   // x @ R
__device__ float g_x  [(size_t)N_NODES * 96];   // inter-layer activations
__device__ float g_out[(size_t)N_NODES * 96];   // aggregated output
__device__ float g_asrc[N_NODES];
__device__ float g_adst[N_NODES];
__device__ float g_m   [N_NODES];               // segment max
__device__ float g_s   [N_NODES];               // segment sum
__device__ float g_w   [TOT_E];                 // per-edge logit -> exp weight
__device__ int   g_src [TOT_E];
__device__ int   g_dst [TOT_E];
__device__ int   g_ei_is64;                     // edge_index dtype flag

// ---------------------------------------------------------------------------
// dtype probe: if buffer is int64 (little-endian, values < 2^31), every odd
// int32 word (high half) is 0.  Reads stay within the first 1.6M int32 words,
// which exist under BOTH interpretations -> always in-bounds.
// ---------------------------------------------------------------------------
__global__ void detect_ei_dtype(const int* __restrict__ w) {
    if (blockIdx.x != 0 || threadIdx.x != 0) return;
    int is64 = 1;
    for (int i = 1; i < 4096; i += 2)
        if (w[i] != 0) { is64 = 0; break; }
    g_ei_is64 = is64;
}

// ---------------------------------------------------------------------------
// edge index prep: int32 or int64 -> int32 (clamped), append self loops.
// ---------------------------------------------------------------------------
__global__ void prep_edges(const void* __restrict__ eiv) {
    int i = blockIdx.x * blockDim.x + threadIdx.x;
    if (i >= TOT_E) return;
    if (i < N_EDGES) {
        long long s, d;
        if (g_ei_is64) {
            const long long* e64 = (const long long*)eiv;
            s = e64[i];
            d = e64[(size_t)N_EDGES + i];
        } else {
            const int* e32 = (const int*)eiv;
            s = e32[i];
            d = e32[(size_t)N_EDGES + i];
        }
        s = s < 0 ? 0 : (s >= N_NODES ? N_NODES - 1 : s);
        d = d < 0 ? 0 : (d >= N_NODES ? N_NODES - 1 : d);
        g_src[i] = (int)s;
        g_dst[i] = (int)d;
    } else {
        int v = i - N_EDGES;
        g_src[i] = v;
        g_dst[i] = v;
    }
}

// ---------------------------------------------------------------------------
// Fused dual GEMM: g_h = x @ W ; g_res = x @ R.  x:[N,DI], W,R:[DI,DO]
// SRC_GX: read activations from device-global g_x instead of arg pointer.
// ---------------------------------------------------------------------------
template <int DI, int DO, int BY, bool SRC_GX>
__global__ void __launch_bounds__(DO * BY)
gemm_dual(const float* __restrict__ xarg,
          const float* __restrict__ W,
          const float* __restrict__ R) {
    constexpr int BM = 32;
    constexpr int BK = 32;
    constexpr int RI = BM / BY;

    const float* __restrict__ x = SRC_GX ? (const float*)g_x : xarg;

    __shared__ float xs[BM][BK + 1];
    __shared__ float ws[BK][DO];
    __shared__ float rs[BK][DO];

    const int col = threadIdx.x;
    const int ty  = threadIdx.y;
    const int tid = ty * DO + col;
    const int NT  = DO * BY;
    const int row0 = blockIdx.x * BM;

    float acch[RI], accr[RI];
#pragma unroll
    for (int i = 0; i < RI; i++) { acch[i] = 0.f; accr[i] = 0.f; }

    for (int k0 = 0; k0 < DI; k0 += BK) {
        for (int idx = tid; idx < BM * BK; idx += NT) {
            int r = idx >> 5, k = idx & 31;
            int gr = row0 + r;
            xs[r][k] = (gr < N_NODES) ? x[(size_t)gr * DI + k0 + k] : 0.f;
        }
        for (int idx = tid; idx < BK * DO; idx += NT) {
            int k = idx / DO, c = idx - k * DO;
            ws[k][c] = W[(size_t)(k0 + k) * DO + c];
            rs[k][c] = R[(size_t)(k0 + k) * DO + c];
        }
        __syncthreads();

#pragma unroll 8
        for (int kk = 0; kk < BK; kk++) {
            float wv = ws[kk][col];
            float rv = rs[kk][col];
#pragma unroll
            for (int i = 0; i < RI; i++) {
                float xv = xs[ty + i * BY][kk];
                acch[i] = fmaf(xv, wv, acch[i]);
                accr[i] = fmaf(xv, rv, accr[i]);
            }
        }
        __syncthreads();
    }

#pragma unroll
    for (int i = 0; i < RI; i++) {
        int gr = row0 + ty + i * BY;
        if (gr < N_NODES) {
            g_h  [(size_t)gr * DO + col] = acch[i];
            g_res[(size_t)gr * DO + col] = accr[i];
        }
    }
}

// ---------------------------------------------------------------------------
// alpha_src / alpha_dst : per-node dot of h row with attention vectors.
// One warp per node row.
// ---------------------------------------------------------------------------
template <int DO>
__global__ void alpha_kernel(const float* __restrict__ a_s,
                             const float* __restrict__ a_d) {
    int gw   = (blockIdx.x * blockDim.x + threadIdx.x) >> 5;
    int lane = threadIdx.x & 31;
    if (gw >= N_NODES) return;
    float sv = 0.f, dv = 0.f;
#pragma unroll
    for (int c = lane; c < DO; c += 32) {
        float hv = g_h[(size_t)gw * DO + c];
        sv = fmaf(hv, a_s[c], sv);
        dv = fmaf(hv, a_d[c], dv);
    }
#pragma unroll
    for (int o = 16; o; o >>= 1) {
        sv += __shfl_xor_sync(0xffffffffu, sv, o);
        dv += __shfl_xor_sync(0xffffffffu, dv, o);
    }
    if (lane == 0) { g_asrc[gw] = sv; g_adst[gw] = dv; }
}

// ---------------------------------------------------------------------------
// init: out=0, m=-inf, s=0
// ---------------------------------------------------------------------------
__global__ void init_kernel(int total) {
    int i = blockIdx.x * blockDim.x + threadIdx.x;
    if (i < total) g_out[i] = 0.f;
    if (i < N_NODES) {
        g_m[i] = __int_as_float(0xff800000);  // -inf
        g_s[i] = 0.f;
    }
}

// float atomic max (mixed-sign safe; identity = -inf)
__device__ __forceinline__ void atomicMaxFloat(float* addr, float value) {
    if (value >= 0.f)
        atomicMax((int*)addr, __float_as_int(value));
    else
        atomicMin((unsigned int*)addr, __float_as_uint(value));
}

// ---------------------------------------------------------------------------
// pass 1: e = leaky_relu(asrc[src] + adst[dst]); segment max into g_m
// ---------------------------------------------------------------------------
__global__ void edge_logits() {
    int i = blockIdx.x * blockDim.x + threadIdx.x;
    if (i >= TOT_E) return;
    int src = g_src[i], dst = g_dst[i];
    float v = g_asrc[src] + g_adst[dst];
    v = (v > 0.f) ? v : NEG_SLOPE * v;
    g_w[i] = v;
    atomicMaxFloat(&g_m[dst], v);
}

// ---------------------------------------------------------------------------
// pass 2: w = exp(e - m[dst]); segment sum into g_s
// ---------------------------------------------------------------------------
__global__ void edge_exp() {
    int i = blockIdx.x * blockDim.x + threadIdx.x;
    if (i >= TOT_E) return;
    int dst = g_dst[i];
    float val = expf(g_w[i] - g_m[dst]);
    g_w[i] = val;
    atomicAdd(&g_s[dst], val);
}

// ---------------------------------------------------------------------------
// pass 3: out[dst] += h[src] * (w / s[dst]).  One warp per edge, lanes over
// feature dim (coalesced row reads; h is L2 resident).
// ---------------------------------------------------------------------------
template <int DO>
__global__ void aggregate_kernel() {
    int gw   = (blockIdx.x * blockDim.x + threadIdx.x) >> 5;
    int lane = threadIdx.x & 31;
    if (gw >= TOT_E) return;
    int src = g_src[gw], dst = g_dst[gw];
    float alpha = g_w[gw] / g_s[dst];
    const float* hp = g_h + (size_t)src * DO;
    float* op = g_out + (size_t)dst * DO;
#pragma unroll
    for (int c = lane; c < DO; c += 32)
        atomicAdd(&op[c], hp[c] * alpha);
}

// ---------------------------------------------------------------------------
// epilogue: x_next = relu(out) + res.  DST_GX: write device-global g_x.
// ---------------------------------------------------------------------------
template <bool DST_GX>
__global__ void combine_kernel(float* __restrict__ xout, int total) {
    int i = blockIdx.x * blockDim.x + threadIdx.x;
    if (i >= total) return;
    float v = g_out[i];
    v = (v > 0.f) ? v : 0.f;
    if (DST_GX) g_x[i]  = v + g_res[i];
    else        xout[i] = v + g_res[i];
}

// ---------------------------------------------------------------------------
// host side
// ---------------------------------------------------------------------------
template <int DI, int DO, bool SRC_GX, bool DST_GX>
static void run_layer(const float* xin,
                      const float* Wp, const float* asp, const float* adp,
                      const float* Rp, float* xout) {
    constexpr int BY = 192 / DO;  // 2 for DO=96, 4 for DO=48
    gemm_dual<DI, DO, BY, SRC_GX><<<(N_NODES + 31) / 32, dim3(DO, BY)>>>(xin, Wp, Rp);
    alpha_kernel<DO><<<(N_NODES + 7) / 8, 256>>>(asp, adp);
    init_kernel<<<(N_NODES * DO + 255) / 256, 256>>>(N_NODES * DO);
    edge_logits<<<(TOT_E + 255) / 256, 256>>>();
    edge_exp<<<(TOT_E + 255) / 256, 256>>>();
    aggregate_kernel<DO><<<(TOT_E + 7) / 8, 256>>>();
    combine_kernel<DST_GX><<<(N_NODES * DO + 255) / 256, 256>>>(xout, N_NODES * DO);
}

extern "C" void kernel_launch(void* const* d_in, const int* in_sizes, int n_in,
                              void* d_out, int out_size) {
    // Expected element counts per tensor name
    const int SZ_X  = N_NODES * 256;
    const int SZ_EI = 2 * N_EDGES;
    const int szW[4] = {256 * 96, 96 * 96, 96 * 96, 96 * 48};
    const int szA[4] = {96, 96, 96, 48};

    // candidate 1: insertion order  x, ei, {W,as,ad,R} x4
    int ins[18]; int p = 0;
    ins[p++] = SZ_X; ins[p++] = SZ_EI;
    for (int i = 0; i < 4; i++) {
        ins[p++] = szW[i]; ins[p++] = szA[i]; ins[p++] = szA[i]; ins[p++] = szW[i];
    }
    // candidate 2: alphabetical  R0..R3, W0..W3, a0d,a0s,...,a3d,a3s, ei, x
    int alp[18]; p = 0;
    for (int i = 0; i < 4; i++) alp[p++] = szW[i];       // R
    for (int i = 0; i < 4; i++) alp[p++] = szW[i];       // W
    for (int i = 0; i < 4; i++) { alp[p++] = szA[i]; alp[p++] = szA[i]; } // a{i}d, a{i}s
    alp[p++] = SZ_EI; alp[p++] = SZ_X;

    bool ins_ok = (n_in == 18), alp_ok = (n_in == 18);
    for (int i = 0; i < 18 && i < n_in; i++) {
        if (in_sizes[i] != ins[i]) ins_ok = false;
        if (in_sizes[i] != alp[i]) alp_ok = false;
    }

    const float* x0; const void* ei;
    const float *W[4], *AS[4], *AD[4], *R[4];

    if (ins_ok || !alp_ok) {   // default to insertion if ambiguous
        x0 = (const float*)d_in[0];
        ei = d_in[1];
        for (int i = 0; i < 4; i++) {
            W [i] = (const float*)d_in[2 + 4 * i];
            AS[i] = (const float*)d_in[3 + 4 * i];
            AD[i] = (const float*)d_in[4 + 4 * i];
            R [i] = (const float*)d_in[5 + 4 * i];
        }
    } else {
        for (int i = 0; i < 4; i++) {
            R [i] = (const float*)d_in[i];
            W [i] = (const float*)d_in[4 + i];
            AD[i] = (const float*)d_in[8 + 2 * i];
            AS[i] = (const float*)d_in[9 + 2 * i];
        }
        ei = d_in[16];
        x0 = (const float*)d_in[17];
    }

    detect_ei_dtype<<<1, 1>>>((const int*)ei);
    prep_edges<<<(TOT_E + 255) / 256, 256>>>(ei);

    run_layer<256, 96, false, true >(x0,      W[0], AS[0], AD[0], R[0], nullptr);
    run_layer< 96, 96, true,  true >(nullptr, W[1], AS[1], AD[1], R[1], nullptr);
    run_layer< 96, 96, true,  true >(nullptr, W[2], AS[2], AD[2], R[2], nullptr);
    run_layer< 96, 48, true,  false>(nullptr, W[3], AS[3], AD[3], R[3], (float*)d_out);
}

// round 7
// speedup vs baseline: 1.5317x; 1.5317x over previous
#include <cuda_runtime.h>
#include <cuda_bf16.h>
#include <cstddef>

// ---------------------------------------------------------------------------
// GAT_29437705846970: 4-layer GATConv (PyG semantics) + residual projection.
//   layer dims: 256->96, 96->96, 96->96, 96->48
//   N = 50000 nodes, E = 800000 edges (+ N self-loops appended)
// Strategy: CSR-by-dst built once, fully fused per-dst softmax+aggregate
// (no float atomics), register accumulation, fused relu+residual epilogue.
// R5 fix: RI rounds UP (DO=48 previously dropped columns 32..47).
// R6: identical resubmit of R5 (round 5 bench was an infra failure).
// ---------------------------------------------------------------------------

constexpr int N_NODES = 50000;
constexpr int N_EDGES = 800000;
constexpr int TOT_E   = N_EDGES + N_NODES;   // edges + self loops
constexpr float NEG_SLOPE = 0.2f;

// ---- scratch (device globals: no allocation allowed) ----------------------
__device__ float g_h  [(size_t)N_NODES * 96];   // h = x @ W
__device__ float g_res[(size_t)N_NODES * 96];   // x @ R
__device__ float g_x  [(size_t)N_NODES * 96];   // inter-layer activations
__device__ float g_asrc[N_NODES];
__device__ float g_adst[N_NODES];
__device__ int   g_src [TOT_E];
__device__ int   g_dst [TOT_E];
__device__ int   g_deg [N_NODES];               // degree count -> scatter cursor
__device__ int   g_rowptr[N_NODES + 1];
__device__ int   g_csr_src[TOT_E];
__device__ int   g_ei_is64;                     // edge_index dtype flag

// ---------------------------------------------------------------------------
// dtype probe: int64 little-endian with values < 2^31 has zero high words.
// Reads first 4096 int32 words — in-bounds under both interpretations.
// ---------------------------------------------------------------------------
__global__ void detect_ei_dtype(const int* __restrict__ w) {
    if (blockIdx.x != 0 || threadIdx.x != 0) return;
    int is64 = 1;
    for (int i = 1; i < 4096; i += 2)
        if (w[i] != 0) { is64 = 0; break; }
    g_ei_is64 = is64;
}

// ---------------------------------------------------------------------------
// edge prep: decode (int32/int64) -> clamped int32, self loops appended,
// zero degree array (separate kernel count_deg consumes it afterwards).
// ---------------------------------------------------------------------------
__global__ void prep_edges(const void* __restrict__ eiv) {
    int i = blockIdx.x * blockDim.x + threadIdx.x;
    if (i < N_NODES) g_deg[i] = 0;
    if (i >= TOT_E) return;
    if (i < N_EDGES) {
        long long s, d;
        if (g_ei_is64) {
            const long long* e64 = (const long long*)eiv;
            s = e64[i];
            d = e64[(size_t)N_EDGES + i];
        } else {
            const int* e32 = (const int*)eiv;
            s = e32[i];
            d = e32[(size_t)N_EDGES + i];
        }
        s = s < 0 ? 0 : (s >= N_NODES ? N_NODES - 1 : s);
        d = d < 0 ? 0 : (d >= N_NODES ? N_NODES - 1 : d);
        g_src[i] = (int)s;
        g_dst[i] = (int)d;
    } else {
        int v = i - N_EDGES;
        g_src[i] = v;
        g_dst[i] = v;
    }
}

__global__ void count_deg() {
    int i = blockIdx.x * blockDim.x + threadIdx.x;
    if (i >= TOT_E) return;
    atomicAdd(&g_deg[g_dst[i]], 1);
}

// ---------------------------------------------------------------------------
// exclusive scan of g_deg -> g_rowptr (single block, 1024 threads, chunked).
// Also resets g_deg to 0 for use as scatter cursor.
// ---------------------------------------------------------------------------
__global__ void __launch_bounds__(1024) scan_deg() {
    __shared__ int ssum[1024];
    const int CH = (N_NODES + 1023) / 1024;   // 49
    int t = threadIdx.x;
    int base = t * CH;
    int s = 0;
    for (int i = 0; i < CH; i++) {
        int idx = base + i;
        if (idx < N_NODES) s += g_deg[idx];
    }
    ssum[t] = s;
    __syncthreads();
    for (int o = 1; o < 1024; o <<= 1) {
        int v = (t >= o) ? ssum[t - o] : 0;
        __syncthreads();
        ssum[t] += v;
        __syncthreads();
    }
    int off = ssum[t] - s;   // exclusive prefix of this chunk
    for (int i = 0; i < CH; i++) {
        int idx = base + i;
        if (idx < N_NODES) {
            int d = g_deg[idx];
            g_rowptr[idx] = off;
            off += d;
            g_deg[idx] = 0;   // reset -> cursor
        }
    }
    if (t == 1023) g_rowptr[N_NODES] = ssum[1023];
}

__global__ void scatter_edges() {
    int i = blockIdx.x * blockDim.x + threadIdx.x;
    if (i >= TOT_E) return;
    int dst = g_dst[i];
    int pos = atomicAdd(&g_deg[dst], 1);
    g_csr_src[g_rowptr[dst] + pos] = g_src[i];
}

// ---------------------------------------------------------------------------
// Fused dual GEMM: g_h = x @ W ; g_res = x @ R.  x:[N,DI], W,R:[DI,DO]
// ---------------------------------------------------------------------------
template <int DI, int DO, int BY, bool SRC_GX>
__global__ void __launch_bounds__(DO * BY)
gemm_dual(const float* __restrict__ xarg,
          const float* __restrict__ W,
          const float* __restrict__ R) {
    constexpr int BM = 32;
    constexpr int BK = 32;
    constexpr int RI = BM / BY;

    const float* __restrict__ x = SRC_GX ? (const float*)g_x : xarg;

    __shared__ float xs[BM][BK + 1];
    __shared__ float ws[BK][DO];
    __shared__ float rs[BK][DO];

    const int col = threadIdx.x;
    const int ty  = threadIdx.y;
    const int tid = ty * DO + col;
    const int NT  = DO * BY;
    const int row0 = blockIdx.x * BM;

    float acch[RI], accr[RI];
#pragma unroll
    for (int i = 0; i < RI; i++) { acch[i] = 0.f; accr[i] = 0.f; }

    for (int k0 = 0; k0 < DI; k0 += BK) {
        for (int idx = tid; idx < BM * BK; idx += NT) {
            int r = idx >> 5, k = idx & 31;
            int gr = row0 + r;
            xs[r][k] = (gr < N_NODES) ? x[(size_t)gr * DI + k0 + k] : 0.f;
        }
        for (int idx = tid; idx < BK * DO; idx += NT) {
            int k = idx / DO, c = idx - k * DO;
            ws[k][c] = W[(size_t)(k0 + k) * DO + c];
            rs[k][c] = R[(size_t)(k0 + k) * DO + c];
        }
        __syncthreads();

#pragma unroll 8
        for (int kk = 0; kk < BK; kk++) {
            float wv = ws[kk][col];
            float rv = rs[kk][col];
#pragma unroll
            for (int i = 0; i < RI; i++) {
                float xv = xs[ty + i * BY][kk];
                acch[i] = fmaf(xv, wv, acch[i]);
                accr[i] = fmaf(xv, rv, accr[i]);
            }
        }
        __syncthreads();
    }

#pragma unroll
    for (int i = 0; i < RI; i++) {
        int gr = row0 + ty + i * BY;
        if (gr < N_NODES) {
            g_h  [(size_t)gr * DO + col] = acch[i];
            g_res[(size_t)gr * DO + col] = accr[i];
        }
    }
}

// ---------------------------------------------------------------------------
// alpha_src / alpha_dst : per-node dot of h row with attention vectors.
// ---------------------------------------------------------------------------
template <int DO>
__global__ void alpha_kernel(const float* __restrict__ a_s,
                             const float* __restrict__ a_d) {
    int gw   = (blockIdx.x * blockDim.x + threadIdx.x) >> 5;
    int lane = threadIdx.x & 31;
    if (gw >= N_NODES) return;
    float sv = 0.f, dv = 0.f;
#pragma unroll
    for (int c = lane; c < DO; c += 32) {
        float hv = g_h[(size_t)gw * DO + c];
        sv = fmaf(hv, a_s[c], sv);
        dv = fmaf(hv, a_d[c], dv);
    }
#pragma unroll
    for (int o = 16; o; o >>= 1) {
        sv += __shfl_xor_sync(0xffffffffu, sv, o);
        dv += __shfl_xor_sync(0xffffffffu, dv, o);
    }
    if (lane == 0) { g_asrc[gw] = sv; g_adst[gw] = dv; }
}

// ---------------------------------------------------------------------------
// Fused softmax + aggregate + relu + residual, one warp per dst node.
// Fast path (deg <= TILE, ~all nodes): logits cached in smem, single gather.
// Slow path: 3-pass streaming (any degree).  No float atomics anywhere.
// RI rounds UP; c < DO predicates handle DO=48.
// ---------------------------------------------------------------------------
template <int DO, bool DST_GX>
__global__ void __launch_bounds__(256)
fused_agg(float* __restrict__ xout) {
    constexpr int TILE  = 64;
    constexpr int WARPS = 8;
    constexpr int RI    = (DO + 31) / 32;   // ceil: DO=48 -> 2
    __shared__ float sw  [WARPS][TILE];
    __shared__ int   ssrc[WARPS][TILE];

    const int warp = threadIdx.x >> 5;
    const int lane = threadIdx.x & 31;
    const int node = blockIdx.x * WARPS + warp;
    if (node >= N_NODES) return;

    const int beg = g_rowptr[node];
    const int end = g_rowptr[node + 1];
    const int deg = end - beg;
    const float adst = g_adst[node];

    float acc[RI];
#pragma unroll
    for (int i = 0; i < RI; i++) acc[i] = 0.f;

    if (deg <= TILE) {
        // ---- fast path: one gather of src ids + logits into smem ----
        float mx = -3.4e38f;
        for (int e = lane; e < deg; e += 32) {
            int s = g_csr_src[beg + e];
            float v = g_asrc[s] + adst;
            v = (v > 0.f) ? v : NEG_SLOPE * v;
            ssrc[warp][e] = s;
            sw  [warp][e] = v;
            mx = fmaxf(mx, v);
        }
#pragma unroll
        for (int o = 16; o; o >>= 1) mx = fmaxf(mx, __shfl_xor_sync(0xffffffffu, mx, o));

        float sum = 0.f;
        __syncwarp();
        for (int e = lane; e < deg; e += 32) {
            float w = __expf(sw[warp][e] - mx);
            sw[warp][e] = w;
            sum += w;
        }
#pragma unroll
        for (int o = 16; o; o >>= 1) sum += __shfl_xor_sync(0xffffffffu, sum, o);
        const float inv = 1.f / sum;

        __syncwarp();
        for (int e = 0; e < deg; e++) {
            const float a = sw[warp][e] * inv;
            const float* hp = g_h + (size_t)ssrc[warp][e] * DO;
#pragma unroll
            for (int i = 0; i < RI; i++) {
                int c = lane + 32 * i;
                if (c < DO) acc[i] = fmaf(hp[c], a, acc[i]);
            }
        }
    } else {
        // ---- generic path ----
        float mx = -3.4e38f;
        for (int e = beg + lane; e < end; e += 32) {
            float v = g_asrc[g_csr_src[e]] + adst;
            v = (v > 0.f) ? v : NEG_SLOPE * v;
            mx = fmaxf(mx, v);
        }
#pragma unroll
        for (int o = 16; o; o >>= 1) mx = fmaxf(mx, __shfl_xor_sync(0xffffffffu, mx, o));

        float sum = 0.f;
        for (int e = beg + lane; e < end; e += 32) {
            float v = g_asrc[g_csr_src[e]] + adst;
            v = (v > 0.f) ? v : NEG_SLOPE * v;
            sum += __expf(v - mx);
        }
#pragma unroll
        for (int o = 16; o; o >>= 1) sum += __shfl_xor_sync(0xffffffffu, sum, o);
        const float inv = 1.f / sum;

        for (int t0 = beg; t0 < end; t0 += TILE) {
            const int cnt = min(TILE, end - t0);
            for (int e = lane; e < cnt; e += 32) {
                int s = g_csr_src[t0 + e];
                float v = g_asrc[s] + adst;
                v = (v > 0.f) ? v : NEG_SLOPE * v;
                sw  [warp][e] = __expf(v - mx) * inv;
                ssrc[warp][e] = s;
            }
            __syncwarp();
            for (int e = 0; e < cnt; e++) {
                const float a = sw[warp][e];
                const float* hp = g_h + (size_t)ssrc[warp][e] * DO;
#pragma unroll
                for (int i = 0; i < RI; i++) {
                    int c = lane + 32 * i;
                    if (c < DO) acc[i] = fmaf(hp[c], a, acc[i]);
                }
            }
            __syncwarp();
        }
    }

    // epilogue: relu + residual
    const size_t o = (size_t)node * DO;
#pragma unroll
    for (int i = 0; i < RI; i++) {
        int c = lane + 32 * i;
        if (c < DO) {
            float v = acc[i] > 0.f ? acc[i] : 0.f;
            v += g_res[o + c];
            if (DST_GX) g_x[o + c]  = v;
            else        xout[o + c] = v;
        }
    }
}

// ---------------------------------------------------------------------------
// host side
// ---------------------------------------------------------------------------
template <int DI, int DO, bool SRC_GX, bool DST_GX>
static void run_layer(const float* xin,
                      const float* Wp, const float* asp, const float* adp,
                      const float* Rp, float* xout) {
    constexpr int BY = 192 / DO;  // 2 for DO=96, 4 for DO=48
    gemm_dual<DI, DO, BY, SRC_GX><<<(N_NODES + 31) / 32, dim3(DO, BY)>>>(xin, Wp, Rp);
    alpha_kernel<DO><<<(N_NODES + 7) / 8, 256>>>(asp, adp);
    fused_agg<DO, DST_GX><<<(N_NODES + 7) / 8, 256>>>(xout);
}

extern "C" void kernel_launch(void* const* d_in, const int* in_sizes, int n_in,
                              void* d_out, int out_size) {
    // ---- input layout detection (size-signature match) ----
    const int SZ_X  = N_NODES * 256;
    const int SZ_EI = 2 * N_EDGES;
    const int szW[4] = {256 * 96, 96 * 96, 96 * 96, 96 * 48};
    const int szA[4] = {96, 96, 96, 48};

    int ins[18]; int p = 0;
    ins[p++] = SZ_X; ins[p++] = SZ_EI;
    for (int i = 0; i < 4; i++) {
        ins[p++] = szW[i]; ins[p++] = szA[i]; ins[p++] = szA[i]; ins[p++] = szW[i];
    }
    int alp[18]; p = 0;
    for (int i = 0; i < 4; i++) alp[p++] = szW[i];                        // R0..R3
    for (int i = 0; i < 4; i++) alp[p++] = szW[i];                        // W0..W3
    for (int i = 0; i < 4; i++) { alp[p++] = szA[i]; alp[p++] = szA[i]; } // a{i}d, a{i}s
    alp[p++] = SZ_EI; alp[p++] = SZ_X;

    bool ins_ok = (n_in == 18), alp_ok = (n_in == 18);
    for (int i = 0; i < 18 && i < n_in; i++) {
        if (in_sizes[i] != ins[i]) ins_ok = false;
        if (in_sizes[i] != alp[i]) alp_ok = false;
    }

    const float* x0; const void* ei;
    const float *W[4], *AS[4], *AD[4], *R[4];

    if (ins_ok || !alp_ok) {
        x0 = (const float*)d_in[0];
        ei = d_in[1];
        for (int i = 0; i < 4; i++) {
            W [i] = (const float*)d_in[2 + 4 * i];
            AS[i] = (const float*)d_in[3 + 4 * i];
            AD[i] = (const float*)d_in[4 + 4 * i];
            R [i] = (const float*)d_in[5 + 4 * i];
        }
    } else {
        for (int i = 0; i < 4; i++) {
            R [i] = (const float*)d_in[i];
            W [i] = (const float*)d_in[4 + i];
            AD[i] = (const float*)d_in[8 + 2 * i];
            AS[i] = (const float*)d_in[9 + 2 * i];
        }
        ei = d_in[16];
        x0 = (const float*)d_in[17];
    }

    // ---- one-time graph preprocessing (per launch) ----
    detect_ei_dtype<<<1, 1>>>((const int*)ei);
    prep_edges<<<(TOT_E + 255) / 256, 256>>>(ei);
    count_deg<<<(TOT_E + 255) / 256, 256>>>();
    scan_deg<<<1, 1024>>>();
    scatter_edges<<<(TOT_E + 255) / 256, 256>>>();

    // ---- 4 GAT layers ----
    run_layer<256, 96, false, true >(x0,      W[0], AS[0], AD[0], R[0], nullptr);
    run_layer< 96, 96, true,  true >(nullptr, W[1], AS[1], AD[1], R[1], nullptr);
    run_layer< 96, 96, true,  true >(nullptr, W[2], AS[2], AD[2], R[2], nullptr);
    run_layer< 96, 48, true,  false>(nullptr, W[3], AS[3], AD[3], R[3], (float*)d_out);
}

// round 8
// speedup vs baseline: 2.3621x; 1.5422x over previous
#include <cuda_runtime.h>
#include <cuda_bf16.h>
#include <cstdint>
#include <cstddef>

// ---------------------------------------------------------------------------
// GAT_29437705846970: 4-layer GATConv + residual projection.
// R8: parallel dtype probe; scan -> atomic offset assignment; 3xTF32
// tensor-core dual GEMM (fp32-accurate); CSR fused aggregate unchanged.
// ---------------------------------------------------------------------------

constexpr int N_NODES = 50000;
constexpr int N_EDGES = 800000;
constexpr int TOT_E   = N_EDGES + N_NODES;
constexpr float NEG_SLOPE = 0.2f;

// ---- scratch (device globals) ---------------------------------------------
__device__ float g_h  [(size_t)N_NODES * 96];
__device__ float g_res[(size_t)N_NODES * 96];
__device__ float g_x  [(size_t)N_NODES * 96];
__device__ float g_asrc[N_NODES];
__device__ float g_adst[N_NODES];
__device__ int   g_src [TOT_E];
__device__ int   g_dst [TOT_E];
__device__ int   g_deg [N_NODES];      // per-dst degree (kept; = segment length)
__device__ int   g_rowptr[N_NODES];    // segment start (order-free allocation)
__device__ int   g_cursor[N_NODES];    // scatter cursor
__device__ int   g_csr_src[TOT_E];
__device__ int   g_total;              // global offset counter
__device__ int   g_ei_is64;

// ---------------------------------------------------------------------------
// detect dtype (parallel probe, block 0) + zero g_deg + zero g_total
// ---------------------------------------------------------------------------
__global__ void detect_and_zero(const int* __restrict__ w) {
    int i = blockIdx.x * blockDim.x + threadIdx.x;
    if (i < N_NODES) g_deg[i] = 0;
    if (i == 0) g_total = 0;
    if (blockIdx.x == 0) {
        int ok = 1;
#pragma unroll
        for (int j = 0; j < 8; j++) {
            int idx = 1 + 2 * (threadIdx.x * 8 + j);   // odd words, < 4096
            if (w[idx] != 0) ok = 0;
        }
        int all = __syncthreads_and(ok);
        if (threadIdx.x == 0) g_ei_is64 = all;
    }
}

// ---------------------------------------------------------------------------
// decode edges (int32/int64, clamped), append self loops, count degrees
// ---------------------------------------------------------------------------
__global__ void prep_edges_count(const void* __restrict__ eiv) {
    int i = blockIdx.x * blockDim.x + threadIdx.x;
    if (i >= TOT_E) return;
    int s, d;
    if (i < N_EDGES) {
        long long sl, dl;
        if (g_ei_is64) {
            const long long* e64 = (const long long*)eiv;
            sl = e64[i];
            dl = e64[(size_t)N_EDGES + i];
        } else {
            const int* e32 = (const int*)eiv;
            sl = e32[i];
            dl = e32[(size_t)N_EDGES + i];
        }
        sl = sl < 0 ? 0 : (sl >= N_NODES ? N_NODES - 1 : sl);
        dl = dl < 0 ? 0 : (dl >= N_NODES ? N_NODES - 1 : dl);
        s = (int)sl; d = (int)dl;
    } else {
        s = d = i - N_EDGES;
    }
    g_src[i] = s;
    g_dst[i] = d;
    atomicAdd(&g_deg[d], 1);
}

// ---------------------------------------------------------------------------
// order-free segment allocation: block-scan degrees, one atomic per block.
// rowptr[i] = segment start; cursor[i] = running scatter index.
// ---------------------------------------------------------------------------
__global__ void __launch_bounds__(256) assign_offsets() {
    __shared__ int warpsum[8];
    __shared__ int basesh;
    int i = blockIdx.x * 256 + threadIdx.x;
    int lane = threadIdx.x & 31, w = threadIdx.x >> 5;
    int deg = (i < N_NODES) ? g_deg[i] : 0;

    int p = deg;                                   // warp inclusive scan
#pragma unroll
    for (int o = 1; o < 32; o <<= 1) {
        int v = __shfl_up_sync(0xffffffffu, p, o);
        if (lane >= o) p += v;
    }
    if (lane == 31) warpsum[w] = p;
    __syncthreads();
    if (w == 0) {
        int s = (lane < 8) ? warpsum[lane] : 0;    // scan warp totals
#pragma unroll
        for (int o = 1; o < 8; o <<= 1) {
            int v = __shfl_up_sync(0xffffffffu, s, o);
            if (lane >= o) s += v;
        }
        if (lane < 8) warpsum[lane] = s;
        if (lane == 7) basesh = atomicAdd(&g_total, s);  // s = block total
    }
    __syncthreads();
    if (i < N_NODES) {
        int off = basesh + (w > 0 ? warpsum[w - 1] : 0) + p - deg;
        g_rowptr[i] = off;
        g_cursor[i] = off;
    }
}

__global__ void scatter_edges() {
    int i = blockIdx.x * blockDim.x + threadIdx.x;
    if (i >= TOT_E) return;
    int pos = atomicAdd(&g_cursor[g_dst[i]], 1);
    g_csr_src[pos] = g_src[i];
}

// ---------------------------------------------------------------------------
// 3xTF32 tensor-core dual GEMM: g_h = x@W, g_res = x@R.
// block: 64 rows x 32 cols, 4 warps (2M x 2N), warp tile 32x16.
// x split hi/lo at fragment load (hi = bits & ~0x1FFF); error ~2^-22.
// ---------------------------------------------------------------------------
__device__ __forceinline__ void mma_tf32(float c[4],
    uint32_t a0, uint32_t a1, uint32_t a2, uint32_t a3,
    uint32_t b0, uint32_t b1) {
    asm volatile(
        "mma.sync.aligned.m16n8k8.row.col.f32.tf32.tf32.f32 "
        "{%0,%1,%2,%3}, {%4,%5,%6,%7}, {%8,%9}, {%0,%1,%2,%3};"
        : "+f"(c[0]), "+f"(c[1]), "+f"(c[2]), "+f"(c[3])
        : "r"(a0), "r"(a1), "r"(a2), "r"(a3), "r"(b0), "r"(b1));
}

__device__ __forceinline__ void split_hi_lo(float f, uint32_t& hi, uint32_t& lo) {
    uint32_t fb = __float_as_uint(f);
    hi = fb & 0xFFFFE000u;
    lo = __float_as_uint(f - __uint_as_float(hi));  // mma truncates lo's tail
}

template <int DI, int DO, bool SRC_GX>
__global__ void __launch_bounds__(128)
gemm_dual_tc(const float* __restrict__ xarg,
             const float* __restrict__ W,
             const float* __restrict__ R) {
    constexpr int BK = 32;
    const float* __restrict__ x = SRC_GX ? (const float*)g_x : xarg;

    __shared__ float xs[64][33];
    __shared__ float ws[BK][33];
    __shared__ float rs[BK][33];

    const int tid  = threadIdx.x;
    const int warp = tid >> 5, lane = tid & 31;
    const int wm = warp & 1, wn = warp >> 1;   // 2x2 warp grid
    const int g  = lane >> 2, tg = lane & 3;   // mma group / thread-in-group
    const int row0 = blockIdx.x * 64;
    const int col0 = blockIdx.y * 32;

    float accW[2][2][4], accR[2][2][4];
#pragma unroll
    for (int a = 0; a < 2; a++)
#pragma unroll
        for (int b = 0; b < 2; b++)
#pragma unroll
            for (int c = 0; c < 4; c++) { accW[a][b][c] = 0.f; accR[a][b][c] = 0.f; }

    for (int k0 = 0; k0 < DI; k0 += BK) {
        // x tile 64x32 (scalar, coalesced)
#pragma unroll
        for (int i = 0; i < 16; i++) {
            int linear = tid + i * 128;        // 0..2047
            int r = linear >> 5, c = linear & 31;
            int gr = row0 + r;
            xs[r][c] = (gr < N_NODES) ? x[(size_t)gr * DI + k0 + c] : 0.f;
        }
        // W/R tiles 32x32
#pragma unroll
        for (int i = 0; i < 8; i++) {
            int linear = tid + i * 128;        // 0..1023
            int kk = linear >> 5, c = linear & 31;
            int gc = col0 + c;
            ws[kk][c] = (gc < DO) ? W[(size_t)(k0 + kk) * DO + gc] : 0.f;
            rs[kk][c] = (gc < DO) ? R[(size_t)(k0 + kk) * DO + gc] : 0.f;
        }
        __syncthreads();

#pragma unroll
        for (int ks = 0; ks < BK; ks += 8) {
            uint32_t ahi[2][4], alo[2][4];
#pragma unroll
            for (int mt = 0; mt < 2; mt++) {
                int rb = wm * 32 + mt * 16;
                float a0 = xs[rb + g     ][ks + tg    ];
                float a1 = xs[rb + g + 8 ][ks + tg    ];
                float a2 = xs[rb + g     ][ks + tg + 4];
                float a3 = xs[rb + g + 8 ][ks + tg + 4];
                split_hi_lo(a0, ahi[mt][0], alo[mt][0]);
                split_hi_lo(a1, ahi[mt][1], alo[mt][1]);
                split_hi_lo(a2, ahi[mt][2], alo[mt][2]);
                split_hi_lo(a3, ahi[mt][3], alo[mt][3]);
            }
#pragma unroll
            for (int h = 0; h < 2; h++) {
                int nb = wn * 16 + h * 8 + g;
                uint32_t wh0, wl0, wh1, wl1, rh0, rl0, rh1, rl1;
                split_hi_lo(ws[ks + tg    ][nb], wh0, wl0);
                split_hi_lo(ws[ks + tg + 4][nb], wh1, wl1);
                split_hi_lo(rs[ks + tg    ][nb], rh0, rl0);
                split_hi_lo(rs[ks + tg + 4][nb], rh1, rl1);
#pragma unroll
                for (int mt = 0; mt < 2; mt++) {
                    mma_tf32(accW[mt][h], ahi[mt][0], ahi[mt][1], ahi[mt][2], ahi[mt][3], wh0, wh1);
                    mma_tf32(accW[mt][h], alo[mt][0], alo[mt][1], alo[mt][2], alo[mt][3], wh0, wh1);
                    mma_tf32(accW[mt][h], ahi[mt][0], ahi[mt][1], ahi[mt][2], ahi[mt][3], wl0, wl1);
                    mma_tf32(accR[mt][h], ahi[mt][0], ahi[mt][1], ahi[mt][2], ahi[mt][3], rh0, rh1);
                    mma_tf32(accR[mt][h], alo[mt][0], alo[mt][1], alo[mt][2], alo[mt][3], rh0, rh1);
                    mma_tf32(accR[mt][h], ahi[mt][0], ahi[mt][1], ahi[mt][2], ahi[mt][3], rl0, rl1);
                }
            }
        }
        __syncthreads();
    }

    // store (c0 even, DO even -> c0 < DO implies c0+1 < DO)
#pragma unroll
    for (int mt = 0; mt < 2; mt++)
#pragma unroll
        for (int h = 0; h < 2; h++) {
            int r0 = row0 + wm * 32 + mt * 16 + g;
            int c0 = col0 + wn * 16 + h * 8 + 2 * tg;
            if (c0 < DO) {
                if (r0 < N_NODES) {
                    g_h  [(size_t)r0 * DO + c0    ] = accW[mt][h][0];
                    g_h  [(size_t)r0 * DO + c0 + 1] = accW[mt][h][1];
                    g_res[(size_t)r0 * DO + c0    ] = accR[mt][h][0];
                    g_res[(size_t)r0 * DO + c0 + 1] = accR[mt][h][1];
                }
                int r1 = r0 + 8;
                if (r1 < N_NODES) {
                    g_h  [(size_t)r1 * DO + c0    ] = accW[mt][h][2];
                    g_h  [(size_t)r1 * DO + c0 + 1] = accW[mt][h][3];
                    g_res[(size_t)r1 * DO + c0    ] = accR[mt][h][2];
                    g_res[(size_t)r1 * DO + c0 + 1] = accR[mt][h][3];
                }
            }
        }
}

// ---------------------------------------------------------------------------
// alpha_src / alpha_dst : per-node dot of h row with attention vectors.
// ---------------------------------------------------------------------------
template <int DO>
__global__ void alpha_kernel(const float* __restrict__ a_s,
                             const float* __restrict__ a_d) {
    int gw   = (blockIdx.x * blockDim.x + threadIdx.x) >> 5;
    int lane = threadIdx.x & 31;
    if (gw >= N_NODES) return;
    float sv = 0.f, dv = 0.f;
#pragma unroll
    for (int c = lane; c < DO; c += 32) {
        float hv = g_h[(size_t)gw * DO + c];
        sv = fmaf(hv, a_s[c], sv);
        dv = fmaf(hv, a_d[c], dv);
    }
#pragma unroll
    for (int o = 16; o; o >>= 1) {
        sv += __shfl_xor_sync(0xffffffffu, sv, o);
        dv += __shfl_xor_sync(0xffffffffu, dv, o);
    }
    if (lane == 0) { g_asrc[gw] = sv; g_adst[gw] = dv; }
}

// ---------------------------------------------------------------------------
// Fused softmax + aggregate + relu + residual, one warp per dst node.
// ---------------------------------------------------------------------------
template <int DO, bool DST_GX>
__global__ void __launch_bounds__(256)
fused_agg(float* __restrict__ xout) {
    constexpr int TILE  = 64;
    constexpr int WARPS = 8;
    constexpr int RI    = (DO + 31) / 32;
    __shared__ float sw  [WARPS][TILE];
    __shared__ int   ssrc[WARPS][TILE];

    const int warp = threadIdx.x >> 5;
    const int lane = threadIdx.x & 31;
    const int node = blockIdx.x * WARPS + warp;
    if (node >= N_NODES) return;

    const int beg = g_rowptr[node];
    const int deg = g_deg[node];
    const int end = beg + deg;
    const float adst = g_adst[node];

    float acc[RI];
#pragma unroll
    for (int i = 0; i < RI; i++) acc[i] = 0.f;

    if (deg <= TILE) {
        float mx = -3.4e38f;
        for (int e = lane; e < deg; e += 32) {
            int s = g_csr_src[beg + e];
            float v = g_asrc[s] + adst;
            v = (v > 0.f) ? v : NEG_SLOPE * v;
            ssrc[warp][e] = s;
            sw  [warp][e] = v;
            mx = fmaxf(mx, v);
        }
#pragma unroll
        for (int o = 16; o; o >>= 1) mx = fmaxf(mx, __shfl_xor_sync(0xffffffffu, mx, o));

        float sum = 0.f;
        __syncwarp();
        for (int e = lane; e < deg; e += 32) {
            float w = __expf(sw[warp][e] - mx);
            sw[warp][e] = w;
            sum += w;
        }
#pragma unroll
        for (int o = 16; o; o >>= 1) sum += __shfl_xor_sync(0xffffffffu, sum, o);
        const float inv = 1.f / sum;

        __syncwarp();
        for (int e = 0; e < deg; e++) {
            const float a = sw[warp][e] * inv;
            const float* hp = g_h + (size_t)ssrc[warp][e] * DO;
#pragma unroll
            for (int i = 0; i < RI; i++) {
                int c = lane + 32 * i;
                if (c < DO) acc[i] = fmaf(hp[c], a, acc[i]);
            }
        }
    } else {
        float mx = -3.4e38f;
        for (int e = beg + lane; e < end; e += 32) {
            float v = g_asrc[g_csr_src[e]] + adst;
            v = (v > 0.f) ? v : NEG_SLOPE * v;
            mx = fmaxf(mx, v);
        }
#pragma unroll
        for (int o = 16; o; o >>= 1) mx = fmaxf(mx, __shfl_xor_sync(0xffffffffu, mx, o));

        float sum = 0.f;
        for (int e = beg + lane; e < end; e += 32) {
            float v = g_asrc[g_csr_src[e]] + adst;
            v = (v > 0.f) ? v : NEG_SLOPE * v;
            sum += __expf(v - mx);
        }
#pragma unroll
        for (int o = 16; o; o >>= 1) sum += __shfl_xor_sync(0xffffffffu, sum, o);
        const float inv = 1.f / sum;

        for (int t0 = beg; t0 < end; t0 += TILE) {
            const int cnt = min(TILE, end - t0);
            for (int e = lane; e < cnt; e += 32) {
                int s = g_csr_src[t0 + e];
                float v = g_asrc[s] + adst;
                v = (v > 0.f) ? v : NEG_SLOPE * v;
                sw  [warp][e] = __expf(v - mx) * inv;
                ssrc[warp][e] = s;
            }
            __syncwarp();
            for (int e = 0; e < cnt; e++) {
                const float a = sw[warp][e];
                const float* hp = g_h + (size_t)ssrc[warp][e] * DO;
#pragma unroll
                for (int i = 0; i < RI; i++) {
                    int c = lane + 32 * i;
                    if (c < DO) acc[i] = fmaf(hp[c], a, acc[i]);
                }
            }
            __syncwarp();
        }
    }

    const size_t o = (size_t)node * DO;
#pragma unroll
    for (int i = 0; i < RI; i++) {
        int c = lane + 32 * i;
        if (c < DO) {
            float v = acc[i] > 0.f ? acc[i] : 0.f;
            v += g_res[o + c];
            if (DST_GX) g_x[o + c]  = v;
            else        xout[o + c] = v;
        }
    }
}

// ---------------------------------------------------------------------------
// host side
// ---------------------------------------------------------------------------
template <int DI, int DO, bool SRC_GX, bool DST_GX>
static void run_layer(const float* xin,
                      const float* Wp, const float* asp, const float* adp,
                      const float* Rp, float* xout) {
    dim3 grid((N_NODES + 63) / 64, (DO + 31) / 32);
    gemm_dual_tc<DI, DO, SRC_GX><<<grid, 128>>>(xin, Wp, Rp);
    alpha_kernel<DO><<<(N_NODES + 7) / 8, 256>>>(asp, adp);
    fused_agg<DO, DST_GX><<<(N_NODES + 7) / 8, 256>>>(xout);
}

extern "C" void kernel_launch(void* const* d_in, const int* in_sizes, int n_in,
                              void* d_out, int out_size) {
    // ---- input layout detection (size-signature match) ----
    const int SZ_X  = N_NODES * 256;
    const int SZ_EI = 2 * N_EDGES;
    const int szW[4] = {256 * 96, 96 * 96, 96 * 96, 96 * 48};
    const int szA[4] = {96, 96, 96, 48};

    int ins[18]; int p = 0;
    ins[p++] = SZ_X; ins[p++] = SZ_EI;
    for (int i = 0; i < 4; i++) {
        ins[p++] = szW[i]; ins[p++] = szA[i]; ins[p++] = szA[i]; ins[p++] = szW[i];
    }
    int alp[18]; p = 0;
    for (int i = 0; i < 4; i++) alp[p++] = szW[i];
    for (int i = 0; i < 4; i++) alp[p++] = szW[i];
    for (int i = 0; i < 4; i++) { alp[p++] = szA[i]; alp[p++] = szA[i]; }
    alp[p++] = SZ_EI; alp[p++] = SZ_X;

    bool ins_ok = (n_in == 18), alp_ok = (n_in == 18);
    for (int i = 0; i < 18 && i < n_in; i++) {
        if (in_sizes[i] != ins[i]) ins_ok = false;
        if (in_sizes[i] != alp[i]) alp_ok = false;
    }

    const float* x0; const void* ei;
    const float *W[4], *AS[4], *AD[4], *R[4];

    if (ins_ok || !alp_ok) {
        x0 = (const float*)d_in[0];
        ei = d_in[1];
        for (int i = 0; i < 4; i++) {
            W [i] = (const float*)d_in[2 + 4 * i];
            AS[i] = (const float*)d_in[3 + 4 * i];
            AD[i] = (const float*)d_in[4 + 4 * i];
            R [i] = (const float*)d_in[5 + 4 * i];
        }
    } else {
        for (int i = 0; i < 4; i++) {
            R [i] = (const float*)d_in[i];
            W [i] = (const float*)d_in[4 + i];
            AD[i] = (const float*)d_in[8 + 2 * i];
            AS[i] = (const float*)d_in[9 + 2 * i];
        }
        ei = d_in[16];
        x0 = (const float*)d_in[17];
    }

    // ---- one-time graph preprocessing ----
    detect_and_zero<<<(N_NODES + 255) / 256, 256>>>((const int*)ei);
    prep_edges_count<<<(TOT_E + 255) / 256, 256>>>(ei);
    assign_offsets<<<(N_NODES + 255) / 256, 256>>>();
    scatter_edges<<<(TOT_E + 255) / 256, 256>>>();

    // ---- 4 GAT layers ----
    run_layer<256, 96, false, true >(x0,      W[0], AS[0], AD[0], R[0], nullptr);
    run_layer< 96, 96, true,  true >(nullptr, W[1], AS[1], AD[1], R[1], nullptr);
    run_layer< 96, 96, true,  true >(nullptr, W[2], AS[2], AD[2], R[2], nullptr);
    run_layer< 96, 48, true,  false>(nullptr, W[3], AS[3], AD[3], R[3], (float*)d_out);
}